// round 1
// baseline (speedup 1.0000x reference)
#include <cuda_runtime.h>
#include <math.h>

#define NN 100000
#define EE 1600000
#define GG 128
#define LL 32
#define HH 64
#define DD 256
#define TNW 16

#define NB   ((NN + 255) / 256)     // 391
#define NB16 ((NN + 15) / 16)       // 6250
#define EB   ((EE + 255) / 256)     // 6250
#define RPB  49
#define PB   ((NN + RPB - 1) / RPB) // 2041

// ---------------- scratch (static device globals; no allocation) -------------
__device__ float g_f[NN * HH];
__device__ float g_xw[NN * HH];
__device__ float g_tmp[NN * HH];
__device__ float g_a[(size_t)NN * DD];
__device__ int   g_deg[NN];
__device__ float g_dinv[NN];
__device__ int   g_rowptr[NN];
__device__ int   g_cursor[NN];
__device__ int   g_bsum[NB + 1];
__device__ int   g_col[EE];
__device__ float g_w[EE];
__device__ float g_cnt[GG];
__device__ float g_sum[GG * DD];
__device__ float g_att[GG * DD];
__device__ float g_t[GG * DD];
__device__ float g_p[2 * GG * DD];
__device__ float g_gh[2 * GG * HH];

// ---------------- init / degree / counts ------------------------------------
__global__ void k_init() {
    int i = blockIdx.x * 256 + threadIdx.x;
    if (i < NN) g_deg[i] = 0;
    if (i < GG) g_cnt[i] = 0.f;
    if (i < GG * DD) { g_sum[i] = 0.f; g_att[i] = 0.f; }
}

__global__ void k_deg(const int* __restrict__ ei) {
    int e = blockIdx.x * 256 + threadIdx.x;
    if (e < EE) atomicAdd(&g_deg[ei[EE + e]], 1);
}

__global__ void k_cnt(const int* __restrict__ batch) {
    int n = blockIdx.x * 256 + threadIdx.x;
    if (n < NN) atomicAdd(&g_cnt[batch[n]], 1.f);
}

__global__ void k_dinv() {
    int n = blockIdx.x * 256 + threadIdx.x;
    if (n < NN) g_dinv[n] = rsqrtf((float)g_deg[n] + 1.f);
}

// ---------------- CSR build: scan of degrees + atomic fill -------------------
__global__ void k_scan1() {
    __shared__ int wsum[8];
    int tid = threadIdx.x;
    int i = blockIdx.x * 256 + tid;
    int v = (i < NN) ? g_deg[i] : 0;
    int x = v;
    #pragma unroll
    for (int o = 1; o < 32; o <<= 1) {
        int y = __shfl_up_sync(0xffffffffu, x, o);
        if ((tid & 31) >= o) x += y;
    }
    if ((tid & 31) == 31) wsum[tid >> 5] = x;
    __syncthreads();
    if (tid == 0) {
        int run = 0;
        #pragma unroll
        for (int w = 0; w < 8; w++) { int t = wsum[w]; wsum[w] = run; run += t; }
        g_bsum[blockIdx.x] = run;
    }
    __syncthreads();
    if (i < NN) g_rowptr[i] = (x - v) + wsum[tid >> 5];
}

__global__ void k_scan2() {
    // single thread over NB block sums (391) — trivial
    int run = 0;
    for (int b = 0; b < NB; b++) { int t = g_bsum[b]; g_bsum[b] = run; run += t; }
}

__global__ void k_scan3() {
    int i = blockIdx.x * 256 + threadIdx.x;
    if (i < NN) {
        int r = g_rowptr[i] + g_bsum[i >> 8];
        g_rowptr[i] = r;
        g_cursor[i] = r;
    }
}

__global__ void k_fill(const int* __restrict__ ei) {
    int e = blockIdx.x * 256 + threadIdx.x;
    if (e >= EE) return;
    int src = ei[e];
    int dst = ei[EE + e];
    int pos = atomicAdd(&g_cursor[dst], 1);
    g_col[pos] = src;
    g_w[pos] = g_dinv[src] * g_dinv[dst];
}

// ---------------- pre-layer: feat = gsn(features @ preW + b); a[:,0:64] -----
__global__ void __launch_bounds__(256) k_pre(const float* __restrict__ feats,
                                             const float* __restrict__ W,
                                             const float* __restrict__ b,
                                             const int* __restrict__ batch,
                                             const float* __restrict__ delta) {
    __shared__ float Ws[LL * HH];
    __shared__ float xs[16 * LL];
    int tid = threadIdx.x;
    int r0 = blockIdx.x * 16;
    float4* Ws4 = (float4*)Ws;
    const float4* Wg = (const float4*)W;
    for (int i = tid; i < LL * HH / 4; i += 256) Ws4[i] = Wg[i];
    int nrows = min(16, NN - r0);
    float4* xs4 = (float4*)xs;
    const float4* fg = (const float4*)(feats + (size_t)r0 * LL);
    for (int i = tid; i < nrows * (LL / 4); i += 256) xs4[i] = fg[i];
    __syncthreads();
    int row = tid >> 4, cq = tid & 15;
    if (row >= nrows) return;
    float4 acc = make_float4(0.f, 0.f, 0.f, 0.f);
    #pragma unroll
    for (int k = 0; k < LL; k++) {
        float xv = xs[row * LL + k];
        float4 w = Ws4[k * 16 + cq];
        acc.x += xv * w.x; acc.y += xv * w.y; acc.z += xv * w.z; acc.w += xv * w.w;
    }
    int n = r0 + row;
    float sc = rsqrtf(fmaxf(g_cnt[batch[n]], 1.f));
    float4 bb = ((const float4*)b)[cq];
    float4 v;
    v.x = (acc.x + bb.x) * sc; v.y = (acc.y + bb.y) * sc;
    v.z = (acc.z + bb.z) * sc; v.w = (acc.w + bb.w) * sc;
    ((float4*)g_f)[n * 16 + cq] = v;
    float dd = 1.f + delta[0];
    float4 a0;
    a0.x = v.x * dd; a0.y = v.y * dd; a0.z = v.z * dd; a0.w = v.w * dd;
    ((float4*)g_a)[(size_t)n * 64 + cq] = a0;
}

// ---------------- GCN matmul: xw = f @ W; tmp = xw*dinv^2 + b ---------------
__global__ void __launch_bounds__(256) k_gcn_mm(const float* __restrict__ W,
                                                const float* __restrict__ b) {
    __shared__ float Ws[HH * HH];
    __shared__ float xs[16 * HH];
    int tid = threadIdx.x;
    int r0 = blockIdx.x * 16;
    float4* Ws4 = (float4*)Ws;
    const float4* Wg = (const float4*)W;
    for (int i = tid; i < HH * HH / 4; i += 256) Ws4[i] = Wg[i];
    int nrows = min(16, NN - r0);
    float4* xs4 = (float4*)xs;
    const float4* fg = (const float4*)(g_f + (size_t)r0 * HH);
    for (int i = tid; i < nrows * (HH / 4); i += 256) xs4[i] = fg[i];
    __syncthreads();
    int row = tid >> 4, cq = tid & 15;
    if (row >= nrows) return;
    float4 acc = make_float4(0.f, 0.f, 0.f, 0.f);
    #pragma unroll
    for (int k = 0; k < HH; k++) {
        float xv = xs[row * HH + k];
        float4 w = Ws4[k * 16 + cq];
        acc.x += xv * w.x; acc.y += xv * w.y; acc.z += xv * w.z; acc.w += xv * w.w;
    }
    int n = r0 + row;
    float di = g_dinv[n];
    float d2 = di * di;
    float4 bb = ((const float4*)b)[cq];
    ((float4*)g_xw)[n * 16 + cq] = acc;
    float4 t;
    t.x = acc.x * d2 + bb.x; t.y = acc.y * d2 + bb.y;
    t.z = acc.z * d2 + bb.z; t.w = acc.w * d2 + bb.w;
    ((float4*)g_tmp)[n * 16 + cq] = t;
}

// ---------------- GCN neighbor gather (CSR, no atomics) ----------------------
__global__ void __launch_bounds__(256) k_gather() {
    int idx = blockIdx.x * 256 + threadIdx.x;
    int n = idx >> 4, cq = idx & 15;
    if (n >= NN) return;
    int s = g_rowptr[n];
    int e = s + g_deg[n];
    const float4* xw4 = (const float4*)g_xw;
    float4 acc = ((float4*)g_tmp)[idx];  // self-loop term + bias
    for (int i = s; i < e; i++) {
        int src = g_col[i];
        float ww = g_w[i];
        float4 v = xw4[src * 16 + cq];
        acc.x += ww * v.x; acc.y += ww * v.y; acc.z += ww * v.z; acc.w += ww * v.w;
    }
    ((float4*)g_tmp)[idx] = acc;
}

// ---------------- combine: f = relu(tmp)+f; write concat part ---------------
__global__ void k_combine(int part) {
    int i = blockIdx.x * 256 + threadIdx.x;
    if (i >= NN * 16) return;
    int n = i >> 4, q = i & 15;
    float4 t = ((float4*)g_tmp)[i];
    float4 f = ((float4*)g_f)[i];
    float4 r;
    r.x = fmaxf(t.x, 0.f) + f.x; r.y = fmaxf(t.y, 0.f) + f.y;
    r.z = fmaxf(t.z, 0.f) + f.z; r.w = fmaxf(t.w, 0.f) + f.w;
    ((float4*)g_f)[i] = r;
    ((float4*)g_a)[(size_t)n * 64 + part * 16 + q] = r;
}

__global__ void k_last() {
    int i = blockIdx.x * 256 + threadIdx.x;
    if (i >= NN * 16) return;
    int n = i >> 4, q = i & 15;
    ((float4*)g_a)[(size_t)n * 64 + 48 + q] = ((float4*)g_tmp)[i];
}

// ---------------- pooling: sum pool (sorted batch, flush on change) ---------
__global__ void __launch_bounds__(256) k_sumpool(const int* __restrict__ batch) {
    int r0 = blockIdx.x * RPB;
    if (r0 >= NN) return;
    int r1 = min(r0 + RPB, NN);
    int tid = threadIdx.x;
    float acc = 0.f;
    int curg = batch[r0];
    for (int r = r0; r < r1; r++) {
        int g = batch[r];
        if (g != curg) {
            atomicAdd(&g_sum[curg * DD + tid], acc);
            acc = 0.f; curg = g;
        }
        acc += g_a[(size_t)r * DD + tid];
    }
    atomicAdd(&g_sum[curg * DD + tid], acc);
}

// ---------------- ctx = tanh((sum/cnt) @ attW) -------------------------------
__global__ void __launch_bounds__(256) k_ctx(const float* __restrict__ attW) {
    __shared__ float srow[DD];
    int g = blockIdx.x, tid = threadIdx.x;
    float c = fmaxf(g_cnt[g], 1.f);
    srow[tid] = g_sum[g * DD + tid] / c;
    __syncthreads();
    float acc = 0.f;
    for (int k = 0; k < DD; k++) acc += srow[k] * attW[k * DD + tid];
    g_t[g * DD + tid] = tanhf(acc);
}

// ---------------- attention pool --------------------------------------------
__global__ void __launch_bounds__(256) k_attpool(const int* __restrict__ batch) {
    __shared__ float red[8];
    __shared__ float coefs;
    int r0 = blockIdx.x * RPB;
    if (r0 >= NN) return;
    int r1 = min(r0 + RPB, NN);
    int tid = threadIdx.x;
    int lane = tid & 31, wid = tid >> 5;
    float acc = 0.f;
    int curg = batch[r0];
    float tval = g_t[curg * DD + tid];
    for (int r = r0; r < r1; r++) {
        int g = batch[r];
        if (g != curg) {
            atomicAdd(&g_att[curg * DD + tid], acc);
            acc = 0.f; curg = g;
            tval = g_t[g * DD + tid];
        }
        float v = g_a[(size_t)r * DD + tid];
        float s = v * tval;
        #pragma unroll
        for (int o = 16; o; o >>= 1) s += __shfl_xor_sync(0xffffffffu, s, o);
        if (lane == 0) red[wid] = s;
        __syncthreads();
        if (tid == 0) {
            float t = 0.f;
            #pragma unroll
            for (int i = 0; i < 8; i++) t += red[i];
            coefs = 1.f / (1.f + expf(-t));
        }
        __syncthreads();
        acc += v * coefs;
    }
    atomicAdd(&g_att[curg * DD + tid], acc);
}

// ---------------- mix: p = mu*att + (1-mu)*sum -------------------------------
__global__ void k_mix(int side, const float* __restrict__ mu) {
    int i = blockIdx.x * 256 + threadIdx.x;
    if (i >= GG * DD) return;
    int d = i & (DD - 1);
    float m = mu[d];
    g_p[side * GG * DD + i] = m * g_att[i] + (1.f - m) * g_sum[i];
}

// ---------------- post-MLP: gx/hx = mlp2(p) ---------------------------------
__global__ void __launch_bounds__(128) k_mlp(int side,
                                             const float* __restrict__ W1, const float* __restrict__ b1,
                                             const float* __restrict__ W2, const float* __restrict__ b2) {
    __shared__ float prow[DD];
    __shared__ float hid[128];
    int g = blockIdx.x, tid = threadIdx.x;
    prow[tid] = g_p[side * GG * DD + g * DD + tid];
    prow[tid + 128] = g_p[side * GG * DD + g * DD + tid + 128];
    __syncthreads();
    float h = b1[tid];
    for (int k = 0; k < DD; k++) h += prow[k] * W1[k * 128 + tid];
    hid[tid] = fmaxf(h, 0.f);
    __syncthreads();
    if (tid < HH) {
        float o = b2[tid];
        for (int k = 0; k < 128; k++) o += hid[k] * W2[k * HH + tid];
        g_gh[side * GG * HH + g * HH + tid] = o;
    }
}

// ---------------- final NTN + scoring ----------------------------------------
__global__ void __launch_bounds__(64) k_score(const float* __restrict__ tnW,
                                              const float* __restrict__ tnV,
                                              const float* __restrict__ tnb,
                                              const float* __restrict__ scW1,
                                              const float* __restrict__ scb1,
                                              const float* __restrict__ scW2,
                                              const float* __restrict__ scb2,
                                              const float* __restrict__ alpha,
                                              float* __restrict__ out) {
    __shared__ float gxs[HH], hxs[HH], t1s[TNW], scs[TNW], hid[TNW];
    __shared__ float l2s;
    int g = blockIdx.x, e = threadIdx.x;
    gxs[e] = g_gh[g * HH + e];
    hxs[e] = g_gh[GG * HH + g * HH + e];
    if (e < TNW) t1s[e] = 0.f;
    if (e == 0) l2s = 0.f;
    __syncthreads();
    float acc[TNW];
    #pragma unroll
    for (int k = 0; k < TNW; k++) acc[k] = 0.f;
    for (int d = 0; d < HH; d++) {
        float gd = gxs[d];
        const float4* wp = (const float4*)(tnW + (d * HH + e) * TNW);
        float4 w0 = wp[0], w1 = wp[1], w2 = wp[2], w3 = wp[3];
        acc[0]  += gd * w0.x; acc[1]  += gd * w0.y; acc[2]  += gd * w0.z; acc[3]  += gd * w0.w;
        acc[4]  += gd * w1.x; acc[5]  += gd * w1.y; acc[6]  += gd * w1.z; acc[7]  += gd * w1.w;
        acc[8]  += gd * w2.x; acc[9]  += gd * w2.y; acc[10] += gd * w2.z; acc[11] += gd * w2.w;
        acc[12] += gd * w3.x; acc[13] += gd * w3.y; acc[14] += gd * w3.z; acc[15] += gd * w3.w;
    }
    float hx = hxs[e];
    #pragma unroll
    for (int k = 0; k < TNW; k++) {
        float s = acc[k] * hx;
        #pragma unroll
        for (int o = 16; o; o >>= 1) s += __shfl_xor_sync(0xffffffffu, s, o);
        if ((e & 31) == 0) atomicAdd(&t1s[k], s);
    }
    float df = gxs[e] - hxs[e];
    float s2 = df * df;
    #pragma unroll
    for (int o = 16; o; o >>= 1) s2 += __shfl_xor_sync(0xffffffffu, s2, o);
    if ((e & 31) == 0) atomicAdd(&l2s, s2);
    __syncthreads();
    if (e < TNW) {
        float t2 = tnb[e];
        for (int j = 0; j < HH; j++) t2 += gxs[j] * tnV[e * 2 * HH + j];
        for (int j = 0; j < HH; j++) t2 += hxs[j] * tnV[e * 2 * HH + HH + j];
        scs[e] = fmaxf(t1s[e] + t2, 0.f);
    }
    __syncthreads();
    if (e < TNW) {
        float h = scb1[e];
        for (int j = 0; j < TNW; j++) h += scs[j] * scW1[j * TNW + e];
        hid[e] = fmaxf(h, 0.f);
    }
    __syncthreads();
    if (e == 0) {
        float sc = scb2[0];
        for (int j = 0; j < TNW; j++) sc += hid[j] * scW2[j];
        float l2 = sqrtf(l2s);
        float al = alpha[0];
        out[g] = al * (1.f / (1.f + expf(-sc))) + (1.f - al) * (1.f / (1.f + expf(l2)));
    }
}

// ---------------- launch ------------------------------------------------------
extern "C" void kernel_launch(void* const* d_in, const int* in_sizes, int n_in,
                              void* d_out, int out_size) {
    const int* ei[2]      = { (const int*)d_in[0], (const int*)d_in[1] };
    const int* batch[2]   = { (const int*)d_in[2], (const int*)d_in[3] };
    const float* feats[2] = { (const float*)d_in[4], (const float*)d_in[5] };
    const float* preW  = (const float*)d_in[6];
    const float* preb  = (const float*)d_in[7];
    const float* convW = (const float*)d_in[8];
    const float* convb = (const float*)d_in[9];
    const float* delta = (const float*)d_in[10];
    const float* alpha = (const float*)d_in[11];
    const float* mu    = (const float*)d_in[12];
    const float* attW  = (const float*)d_in[13];
    const float* pW1   = (const float*)d_in[14];
    const float* pb1   = (const float*)d_in[15];
    const float* pW2   = (const float*)d_in[16];
    const float* pb2   = (const float*)d_in[17];
    const float* tnW   = (const float*)d_in[18];
    const float* tnV   = (const float*)d_in[19];
    const float* tnb   = (const float*)d_in[20];
    const float* scW1  = (const float*)d_in[21];
    const float* scb1  = (const float*)d_in[22];
    const float* scW2  = (const float*)d_in[23];
    const float* scb2  = (const float*)d_in[24];
    float* out = (float*)d_out;

    for (int s = 0; s < 2; s++) {
        k_init<<<NB, 256>>>();
        k_deg<<<EB, 256>>>(ei[s]);
        k_cnt<<<NB, 256>>>(batch[s]);
        k_dinv<<<NB, 256>>>();
        k_scan1<<<NB, 256>>>();
        k_scan2<<<1, 1>>>();
        k_scan3<<<NB, 256>>>();
        k_fill<<<EB, 256>>>(ei[s]);
        k_pre<<<NB16, 256>>>(feats[s], preW, preb, batch[s], delta);
        for (int i = 0; i < 3; i++) {
            k_gcn_mm<<<NB16, 256>>>(convW + i * HH * HH, convb + i * HH);
            k_gather<<<NB16, 256>>>();
            if (i < 2) k_combine<<<NB16, 256>>>(i + 1);
            else       k_last<<<NB16, 256>>>();
        }
        k_sumpool<<<PB, 256>>>(batch[s]);
        k_ctx<<<GG, 256>>>(attW);
        k_attpool<<<PB, 256>>>(batch[s]);
        k_mix<<<(GG * DD + 255) / 256, 256>>>(s, mu);
        k_mlp<<<GG, 128>>>(s, pW1, pb1, pW2, pb2);
    }
    k_score<<<GG, 64>>>(tnW, tnV, tnb, scW1, scb1, scW2, scb2, alpha, out);
}

// round 3
// speedup vs baseline: 1.5104x; 1.5104x over previous
#include <cuda_runtime.h>
#include <math.h>

#define NN 100000
#define EE 1600000
#define GG 128
#define LL 32
#define HH 64
#define DD 256
#define TNW 16

#define NB   ((NN + 255) / 256)     // 391
#define EB   ((EE + 255) / 256)     // 6250
#define GB   ((NN + 15) / 16)       // gather blocks: 16 nodes/block
#define MMB  ((NN + 63) / 64)       // 1563 mm blocks
#define SB   6                       // sub-blocks per graph for pooling

// ---------------- scratch (static device globals; no allocation) -------------
__device__ float g_f[NN * HH];
__device__ float g_agg[NN * HH];
__device__ float g_a[(size_t)NN * DD];
__device__ int   g_deg[NN];
__device__ float g_dinv[NN];
__device__ int   g_rowptr[NN];
__device__ int   g_cursor[NN];
__device__ int   g_bsum[512];
__device__ int2  g_cw[EE];
__device__ int   g_gstart[GG + 1];
__device__ float g_sum[GG * DD];
__device__ float g_att[GG * DD];
__device__ float g_t[GG * DD];
__device__ float g_gh[2 * GG * HH];

// ---------------- f32x2 helpers ----------------------------------------------
__device__ __forceinline__ void fma2(unsigned long long& d, unsigned long long a,
                                     unsigned long long b) {
    asm("fma.rn.f32x2 %0, %1, %2, %0;" : "+l"(d) : "l"(a), "l"(b));
}
__device__ __forceinline__ unsigned long long pack2(float lo, float hi) {
    unsigned long long r;
    asm("mov.b64 %0, {%1, %2};" : "=l"(r) : "f"(lo), "f"(hi));
    return r;
}
__device__ __forceinline__ float2 unpack2(unsigned long long v) {
    float2 r;
    asm("mov.b64 {%0, %1}, %2;" : "=f"(r.x), "=f"(r.y) : "l"(v));
    return r;
}

// ---------------- init: zero deg/sum/att + graph start offsets ---------------
__global__ void k_init(const int* __restrict__ batch) {
    int i = blockIdx.x * 256 + threadIdx.x;
    if (i < NN) {
        g_deg[i] = 0;
        int b = batch[i];
        int prev = (i > 0) ? batch[i - 1] : -1;
        for (int g = prev + 1; g <= b; g++) g_gstart[g] = i;
        if (i == NN - 1)
            for (int g = b + 1; g <= GG; g++) g_gstart[g] = NN;
    }
    if (i < GG * DD) { g_sum[i] = 0.f; g_att[i] = 0.f; }
}

__global__ void k_deg(const int* __restrict__ ei) {
    int e = blockIdx.x * 256 + threadIdx.x;
    if (e < EE) atomicAdd(&g_deg[ei[EE + e]], 1);
}

// ---------------- CSR build: scans + atomic fill -----------------------------
__global__ void k_scan1() {
    __shared__ int wsum[8];
    int tid = threadIdx.x;
    int i = blockIdx.x * 256 + tid;
    int v = (i < NN) ? g_deg[i] : 0;
    if (i < NN) g_dinv[i] = rsqrtf((float)v + 1.f);
    int x = v;
    #pragma unroll
    for (int o = 1; o < 32; o <<= 1) {
        int y = __shfl_up_sync(0xffffffffu, x, o);
        if ((tid & 31) >= o) x += y;
    }
    if ((tid & 31) == 31) wsum[tid >> 5] = x;
    __syncthreads();
    if (tid == 0) {
        int run = 0;
        #pragma unroll
        for (int w = 0; w < 8; w++) { int t = wsum[w]; wsum[w] = run; run += t; }
        g_bsum[blockIdx.x] = run;
    }
    __syncthreads();
    if (i < NN) g_rowptr[i] = (x - v) + wsum[tid >> 5];
}

__global__ void __launch_bounds__(512) k_scan2() {
    __shared__ int wsum[16];
    int tid = threadIdx.x;
    int v = (tid < NB) ? g_bsum[tid] : 0;
    int x = v;
    #pragma unroll
    for (int o = 1; o < 32; o <<= 1) {
        int y = __shfl_up_sync(0xffffffffu, x, o);
        if ((tid & 31) >= o) x += y;
    }
    if ((tid & 31) == 31) wsum[tid >> 5] = x;
    __syncthreads();
    if (tid == 0) {
        int run = 0;
        #pragma unroll
        for (int w = 0; w < 16; w++) { int t = wsum[w]; wsum[w] = run; run += t; }
    }
    __syncthreads();
    if (tid < NB) g_bsum[tid] = (x - v) + wsum[tid >> 5];
}

__global__ void k_scan3() {
    int i = blockIdx.x * 256 + threadIdx.x;
    if (i < NN) {
        int r = g_rowptr[i] + g_bsum[i >> 8];
        g_rowptr[i] = r;
        g_cursor[i] = r;
    }
}

__global__ void k_fill(const int* __restrict__ ei) {
    int e = blockIdx.x * 256 + threadIdx.x;
    if (e >= EE) return;
    int src = ei[e];
    int dst = ei[EE + e];
    int pos = atomicAdd(&g_cursor[dst], 1);
    float w = g_dinv[src] * g_dinv[dst];
    g_cw[pos] = make_int2(src, __float_as_int(w));
}

// ---------------- pre-layer: f = gsn(features @ preW + b); a[:,0:64] ---------
__global__ void __launch_bounds__(256) k_pre(const float* __restrict__ feats,
                                             const float* __restrict__ W,
                                             const float* __restrict__ b,
                                             const int* __restrict__ batch,
                                             const float* __restrict__ delta) {
    __shared__ float Ws[LL * HH];
    __shared__ float xs[16 * LL];
    int tid = threadIdx.x;
    int r0 = blockIdx.x * 16;
    float4* Ws4 = (float4*)Ws;
    const float4* Wg = (const float4*)W;
    for (int i = tid; i < LL * HH / 4; i += 256) Ws4[i] = Wg[i];
    int nrows = min(16, NN - r0);
    float4* xs4 = (float4*)xs;
    const float4* fg = (const float4*)(feats + (size_t)r0 * LL);
    for (int i = tid; i < nrows * (LL / 4); i += 256) xs4[i] = fg[i];
    __syncthreads();
    int row = tid >> 4, cq = tid & 15;
    if (row >= nrows) return;
    float4 acc = make_float4(0.f, 0.f, 0.f, 0.f);
    #pragma unroll
    for (int k = 0; k < LL; k++) {
        float xv = xs[row * LL + k];
        float4 w = Ws4[k * 16 + cq];
        acc.x += xv * w.x; acc.y += xv * w.y; acc.z += xv * w.z; acc.w += xv * w.w;
    }
    int n = r0 + row;
    int bg = batch[n];
    float cnt = (float)(g_gstart[bg + 1] - g_gstart[bg]);
    float sc = rsqrtf(fmaxf(cnt, 1.f));
    float4 bb = ((const float4*)b)[cq];
    float4 v;
    v.x = (acc.x + bb.x) * sc; v.y = (acc.y + bb.y) * sc;
    v.z = (acc.z + bb.z) * sc; v.w = (acc.w + bb.w) * sc;
    ((float4*)g_f)[n * 16 + cq] = v;
    float dd = 1.f + delta[0];
    float4 a0;
    a0.x = v.x * dd; a0.y = v.y * dd; a0.z = v.z * dd; a0.w = v.w * dd;
    ((float4*)g_a)[(size_t)n * 64 + cq] = a0;
}

// ---------------- gather on f: agg = sum w*f[src] + dinv^2 * f ---------------
__global__ void __launch_bounds__(256) k_gather() {
    int tid = threadIdx.x;
    int grp = tid >> 4;
    int lane16 = tid & 15;
    int n = blockIdx.x * 16 + grp;
    int s = g_rowptr[n];
    int cnt = g_deg[n];
    const float4* f4 = (const float4*)g_f;
    float di = g_dinv[n];
    float d2 = di * di;
    float4 me = f4[n * 16 + lane16];
    float4 acc = make_float4(me.x * d2, me.y * d2, me.z * d2, me.w * d2);
    unsigned mask = 0xFFFFu << (tid & 16);
    for (int c = 0; c < cnt; c += 16) {
        int idx = c + lane16;
        int2 cw = (idx < cnt) ? g_cw[s + idx] : make_int2(0, 0);
        int lim = min(16, cnt - c);
        for (int j = 0; j < lim; j++) {
            int col = __shfl_sync(mask, cw.x, j, 16);
            float w = __int_as_float(__shfl_sync(mask, cw.y, j, 16));
            float4 v = f4[col * 16 + lane16];
            acc.x += w * v.x; acc.y += w * v.y; acc.z += w * v.z; acc.w += w * v.w;
        }
    }
    ((float4*)g_agg)[n * 16 + lane16] = acc;
}

// ---------------- mm + epilogue: out = agg@W + b; relu/residual/concat -------
__global__ void __launch_bounds__(256) k_mm(const float* __restrict__ W,
                                            const float* __restrict__ b,
                                            int layer) {
    __shared__ float xs[64 * 64];
    __shared__ float ws[64 * 64];
    int t = threadIdx.x;
    int r0 = blockIdx.x * 64;
    int nrows = min(64, NN - r0);
    const float4* Wg = (const float4*)W;
    float4* ws4 = (float4*)ws;
    for (int i = t; i < 1024; i += 256) ws4[i] = Wg[i];
    const float4* ag = (const float4*)g_agg;
    float4* xs4 = (float4*)xs;
    for (int p = 0; p < 4; p++) {
        int idx = p * 256 + t;
        int r = idx >> 4, kq = idx & 15;
        float4 v = (r < nrows) ? ag[(r0 + r) * 16 + kq]
                               : make_float4(0.f, 0.f, 0.f, 0.f);
        xs4[idx] = v;
    }
    __syncthreads();
    int tr = t >> 4, tc = t & 15;
    unsigned long long acc[4][2];
    #pragma unroll
    for (int i = 0; i < 4; i++) { acc[i][0] = 0ull; acc[i][1] = 0ull; }
    #pragma unroll 4
    for (int k = 0; k < 64; k++) {
        float4 wv = ((float4*)ws)[k * 16 + tc];
        unsigned long long w01 = pack2(wv.x, wv.y);
        unsigned long long w23 = pack2(wv.z, wv.w);
        #pragma unroll
        for (int i = 0; i < 4; i++) {
            float xv = xs[(tr * 4 + i) * 64 + k];
            unsigned long long xp = pack2(xv, xv);
            fma2(acc[i][0], xp, w01);
            fma2(acc[i][1], xp, w23);
        }
    }
    float4 bb = ((const float4*)b)[tc];
    #pragma unroll
    for (int i = 0; i < 4; i++) {
        int r = r0 + tr * 4 + i;
        if (r >= NN) continue;
        float2 a0 = unpack2(acc[i][0]);
        float2 a1 = unpack2(acc[i][1]);
        float4 o;
        o.x = a0.x + bb.x; o.y = a0.y + bb.y;
        o.z = a1.x + bb.z; o.w = a1.y + bb.w;
        if (layer < 2) {
            float4 f = ((float4*)g_f)[r * 16 + tc];
            float4 nf;
            nf.x = fmaxf(o.x, 0.f) + f.x; nf.y = fmaxf(o.y, 0.f) + f.y;
            nf.z = fmaxf(o.z, 0.f) + f.z; nf.w = fmaxf(o.w, 0.f) + f.w;
            ((float4*)g_f)[r * 16 + tc] = nf;
            ((float4*)g_a)[(size_t)r * 64 + (layer + 1) * 16 + tc] = nf;
        } else {
            ((float4*)g_a)[(size_t)r * 64 + 48 + tc] = o;
        }
    }
}

// ---------------- sum pool: warp per row, per-graph ranges -------------------
__global__ void __launch_bounds__(256) k_sumpool() {
    __shared__ float sm[8 * 256];
    int g = blockIdx.x;
    int s = g_gstart[g], e = g_gstart[g + 1];
    int wid = threadIdx.x >> 5, lane = threadIdx.x & 31;
    int wg = blockIdx.y * 8 + wid;
    float acc[8];
    #pragma unroll
    for (int j = 0; j < 8; j++) acc[j] = 0.f;
    for (int r = s + wg; r < e; r += SB * 8) {
        const float4* row = (const float4*)(g_a + (size_t)r * DD);
        float4 v0 = row[lane * 2], v1 = row[lane * 2 + 1];
        acc[0] += v0.x; acc[1] += v0.y; acc[2] += v0.z; acc[3] += v0.w;
        acc[4] += v1.x; acc[5] += v1.y; acc[6] += v1.z; acc[7] += v1.w;
    }
    #pragma unroll
    for (int j = 0; j < 8; j++) sm[wid * 256 + lane * 8 + j] = acc[j];
    __syncthreads();
    int t = threadIdx.x;
    float ssum = 0.f;
    #pragma unroll
    for (int w = 0; w < 8; w++) ssum += sm[w * 256 + t];
    atomicAdd(&g_sum[g * DD + t], ssum);
}

// ---------------- ctx = tanh((sum/cnt) @ attW) -------------------------------
__global__ void __launch_bounds__(256) k_ctx(const float* __restrict__ attW) {
    __shared__ float srow[DD];
    int g = blockIdx.x, tid = threadIdx.x;
    float c = fmaxf((float)(g_gstart[g + 1] - g_gstart[g]), 1.f);
    srow[tid] = g_sum[g * DD + tid] / c;
    __syncthreads();
    float acc = 0.f;
    for (int k = 0; k < DD; k++) acc += srow[k] * attW[k * DD + tid];
    g_t[g * DD + tid] = tanhf(acc);
}

// ---------------- attention pool ---------------------------------------------
__global__ void __launch_bounds__(256) k_attpool() {
    __shared__ float sm[8 * 256];
    int g = blockIdx.x;
    int s = g_gstart[g], e = g_gstart[g + 1];
    int wid = threadIdx.x >> 5, lane = threadIdx.x & 31;
    int wg = blockIdx.y * 8 + wid;
    float tval[8];
    #pragma unroll
    for (int j = 0; j < 8; j++) tval[j] = g_t[g * DD + lane * 8 + j];
    float acc[8];
    #pragma unroll
    for (int j = 0; j < 8; j++) acc[j] = 0.f;
    for (int r = s + wg; r < e; r += SB * 8) {
        const float4* row = (const float4*)(g_a + (size_t)r * DD);
        float4 v0 = row[lane * 2], v1 = row[lane * 2 + 1];
        float dot = v0.x * tval[0] + v0.y * tval[1] + v0.z * tval[2] + v0.w * tval[3]
                  + v1.x * tval[4] + v1.y * tval[5] + v1.z * tval[6] + v1.w * tval[7];
        #pragma unroll
        for (int o = 16; o; o >>= 1) dot += __shfl_xor_sync(0xffffffffu, dot, o);
        float coef = 1.f / (1.f + expf(-dot));
        acc[0] += v0.x * coef; acc[1] += v0.y * coef;
        acc[2] += v0.z * coef; acc[3] += v0.w * coef;
        acc[4] += v1.x * coef; acc[5] += v1.y * coef;
        acc[6] += v1.z * coef; acc[7] += v1.w * coef;
    }
    #pragma unroll
    for (int j = 0; j < 8; j++) sm[wid * 256 + lane * 8 + j] = acc[j];
    __syncthreads();
    int t = threadIdx.x;
    float ssum = 0.f;
    #pragma unroll
    for (int w = 0; w < 8; w++) ssum += sm[w * 256 + t];
    atomicAdd(&g_att[g * DD + t], ssum);
}

// ---------------- mix + post-MLP ---------------------------------------------
__global__ void __launch_bounds__(128) k_mlp(int side,
                                             const float* __restrict__ mu,
                                             const float* __restrict__ W1, const float* __restrict__ b1,
                                             const float* __restrict__ W2, const float* __restrict__ b2) {
    __shared__ float prow[DD];
    __shared__ float hid[128];
    int g = blockIdx.x, tid = threadIdx.x;
    {
        float m0 = mu[tid], m1 = mu[tid + 128];
        prow[tid] = m0 * g_att[g * DD + tid] + (1.f - m0) * g_sum[g * DD + tid];
        prow[tid + 128] = m1 * g_att[g * DD + tid + 128] + (1.f - m1) * g_sum[g * DD + tid + 128];
    }
    __syncthreads();
    float h = b1[tid];
    for (int k = 0; k < DD; k++) h += prow[k] * W1[k * 128 + tid];
    hid[tid] = fmaxf(h, 0.f);
    __syncthreads();
    if (tid < HH) {
        float o = b2[tid];
        for (int k = 0; k < 128; k++) o += hid[k] * W2[k * HH + tid];
        g_gh[side * GG * HH + g * HH + tid] = o;
    }
}

// ---------------- final NTN + scoring ----------------------------------------
__global__ void __launch_bounds__(64) k_score(const float* __restrict__ tnW,
                                              const float* __restrict__ tnV,
                                              const float* __restrict__ tnb,
                                              const float* __restrict__ scW1,
                                              const float* __restrict__ scb1,
                                              const float* __restrict__ scW2,
                                              const float* __restrict__ scb2,
                                              const float* __restrict__ alpha,
                                              float* __restrict__ out) {
    __shared__ float gxs[HH], hxs[HH], t1s[TNW], scs[TNW], hid[TNW];
    __shared__ float l2s;
    int g = blockIdx.x, e = threadIdx.x;
    gxs[e] = g_gh[g * HH + e];
    hxs[e] = g_gh[GG * HH + g * HH + e];
    if (e < TNW) t1s[e] = 0.f;
    if (e == 0) l2s = 0.f;
    __syncthreads();
    float acc[TNW];
    #pragma unroll
    for (int k = 0; k < TNW; k++) acc[k] = 0.f;
    for (int d = 0; d < HH; d++) {
        float gd = gxs[d];
        const float4* wp = (const float4*)(tnW + (d * HH + e) * TNW);
        float4 w0 = wp[0], w1 = wp[1], w2 = wp[2], w3 = wp[3];
        acc[0]  += gd * w0.x; acc[1]  += gd * w0.y; acc[2]  += gd * w0.z; acc[3]  += gd * w0.w;
        acc[4]  += gd * w1.x; acc[5]  += gd * w1.y; acc[6]  += gd * w1.z; acc[7]  += gd * w1.w;
        acc[8]  += gd * w2.x; acc[9]  += gd * w2.y; acc[10] += gd * w2.z; acc[11] += gd * w2.w;
        acc[12] += gd * w3.x; acc[13] += gd * w3.y; acc[14] += gd * w3.z; acc[15] += gd * w3.w;
    }
    float hx = hxs[e];
    #pragma unroll
    for (int k = 0; k < TNW; k++) {
        float s = acc[k] * hx;
        #pragma unroll
        for (int o = 16; o; o >>= 1) s += __shfl_xor_sync(0xffffffffu, s, o);
        if ((e & 31) == 0) atomicAdd(&t1s[k], s);
    }
    float df = gxs[e] - hxs[e];
    float s2 = df * df;
    #pragma unroll
    for (int o = 16; o; o >>= 1) s2 += __shfl_xor_sync(0xffffffffu, s2, o);
    if ((e & 31) == 0) atomicAdd(&l2s, s2);
    __syncthreads();
    if (e < TNW) {
        float t2 = tnb[e];
        for (int j = 0; j < HH; j++) t2 += gxs[j] * tnV[e * 2 * HH + j];
        for (int j = 0; j < HH; j++) t2 += hxs[j] * tnV[e * 2 * HH + HH + j];
        scs[e] = fmaxf(t1s[e] + t2, 0.f);
    }
    __syncthreads();
    if (e < TNW) {
        float h = scb1[e];
        for (int j = 0; j < TNW; j++) h += scs[j] * scW1[j * TNW + e];
        hid[e] = fmaxf(h, 0.f);
    }
    __syncthreads();
    if (e == 0) {
        float sc = scb2[0];
        for (int j = 0; j < TNW; j++) sc += hid[j] * scW2[j];
        float l2 = sqrtf(l2s);
        float al = alpha[0];
        out[g] = al * (1.f / (1.f + expf(-sc))) + (1.f - al) * (1.f / (1.f + expf(l2)));
    }
}

// ---------------- launch ------------------------------------------------------
extern "C" void kernel_launch(void* const* d_in, const int* in_sizes, int n_in,
                              void* d_out, int out_size) {
    const int* ei[2]      = { (const int*)d_in[0], (const int*)d_in[1] };
    const int* batch[2]   = { (const int*)d_in[2], (const int*)d_in[3] };
    const float* feats[2] = { (const float*)d_in[4], (const float*)d_in[5] };
    const float* preW  = (const float*)d_in[6];
    const float* preb  = (const float*)d_in[7];
    const float* convW = (const float*)d_in[8];
    const float* convb = (const float*)d_in[9];
    const float* delta = (const float*)d_in[10];
    const float* alpha = (const float*)d_in[11];
    const float* mu    = (const float*)d_in[12];
    const float* attW  = (const float*)d_in[13];
    const float* pW1   = (const float*)d_in[14];
    const float* pb1   = (const float*)d_in[15];
    const float* pW2   = (const float*)d_in[16];
    const float* pb2   = (const float*)d_in[17];
    const float* tnW   = (const float*)d_in[18];
    const float* tnV   = (const float*)d_in[19];
    const float* tnb   = (const float*)d_in[20];
    const float* scW1  = (const float*)d_in[21];
    const float* scb1  = (const float*)d_in[22];
    const float* scW2  = (const float*)d_in[23];
    const float* scb2  = (const float*)d_in[24];
    float* out = (float*)d_out;

    dim3 pgrid(GG, SB);
    for (int s = 0; s < 2; s++) {
        k_init<<<NB, 256>>>(batch[s]);
        k_deg<<<EB, 256>>>(ei[s]);
        k_scan1<<<NB, 256>>>();
        k_scan2<<<1, 512>>>();
        k_scan3<<<NB, 256>>>();
        k_fill<<<EB, 256>>>(ei[s]);
        k_pre<<<(NN + 15) / 16, 256>>>(feats[s], preW, preb, batch[s], delta);
        for (int i = 0; i < 3; i++) {
            k_gather<<<GB, 256>>>();
            k_mm<<<MMB, 256>>>(convW + i * HH * HH, convb + i * HH, i);
        }
        k_sumpool<<<pgrid, 256>>>();
        k_ctx<<<GG, 256>>>(attW);
        k_attpool<<<pgrid, 256>>>();
        k_mlp<<<GG, 128>>>(s, mu, pW1, pb1, pW2, pb2);
    }
    k_score<<<GG, 64>>>(tnW, tnV, tnb, scW1, scb1, scW2, scb2, alpha, out);
}

// round 4
// speedup vs baseline: 1.5987x; 1.0584x over previous
#include <cuda_runtime.h>
#include <cuda_bf16.h>
#include <math.h>

#define NN 100000
#define EE 1600000
#define GG 128
#define LL 32
#define HH 64
#define DD 256
#define TNW 16

#define NB   ((NN + 255) / 256)     // 391
#define EB   ((EE + 255) / 256)     // 6250
#define GB   (NN / 16)              // 6250 gather blocks (16 nodes each; NN%16==0)
#define MMB  ((NN + 63) / 64)       // 1563
#define SB   6                      // sub-blocks per graph for pooling

// ---------------- scratch (static device globals; no allocation) -------------
__device__ float         g_f[2 * NN * HH];
__device__ __nv_bfloat16 g_xwb[2 * NN * HH];
__device__ float         g_a[2 * (size_t)NN * DD];
__device__ int   g_deg[2 * NN];
__device__ float g_dinv[2 * NN];
__device__ int   g_rowptr[2 * NN];
__device__ int   g_cursor[2 * NN];
__device__ int   g_bsum[2 * 512];
__device__ int2  g_cw[2 * EE];
__device__ int   g_gstart[2 * (GG + 1)];
__device__ float g_sum[2 * GG * DD];
__device__ float g_att[2 * GG * DD];
__device__ float g_t[2 * GG * DD];
__device__ float g_gh[2 * GG * HH];

// ---------------- f32x2 helpers ----------------------------------------------
__device__ __forceinline__ void fma2(unsigned long long& d, unsigned long long a,
                                     unsigned long long b) {
    asm("fma.rn.f32x2 %0, %1, %2, %0;" : "+l"(d) : "l"(a), "l"(b));
}
__device__ __forceinline__ unsigned long long pack2(float lo, float hi) {
    unsigned long long r;
    asm("mov.b64 %0, {%1, %2};" : "=l"(r) : "f"(lo), "f"(hi));
    return r;
}
__device__ __forceinline__ float2 unpack2(unsigned long long v) {
    float2 r;
    asm("mov.b64 {%0, %1}, %2;" : "=f"(r.x), "=f"(r.y) : "l"(v));
    return r;
}

// ---------------- init: zero deg/sum/att + graph start offsets ---------------
__global__ void k_init(const int* __restrict__ b1, const int* __restrict__ b2) {
    int side = blockIdx.y;
    const int* batch = side ? b2 : b1;
    int i = blockIdx.x * 256 + threadIdx.x;
    if (i < NN) {
        g_deg[side * NN + i] = 0;
        int b = batch[i];
        int prev = (i > 0) ? batch[i - 1] : -1;
        for (int g = prev + 1; g <= b; g++) g_gstart[side * (GG + 1) + g] = i;
        if (i == NN - 1)
            for (int g = b + 1; g <= GG; g++) g_gstart[side * (GG + 1) + g] = NN;
    }
    if (i < GG * DD) { g_sum[side * GG * DD + i] = 0.f; g_att[side * GG * DD + i] = 0.f; }
}

__global__ void k_deg(const int* __restrict__ e1, const int* __restrict__ e2) {
    int side = blockIdx.y;
    const int* ei = side ? e2 : e1;
    int e = blockIdx.x * 256 + threadIdx.x;
    if (e < EE) atomicAdd(&g_deg[side * NN + ei[EE + e]], 1);
}

// ---------------- CSR build: scans + atomic fill -----------------------------
__global__ void k_scan1() {
    __shared__ int wsum[8];
    int side = blockIdx.y;
    int tid = threadIdx.x;
    int i = blockIdx.x * 256 + tid;
    int v = (i < NN) ? g_deg[side * NN + i] : 0;
    if (i < NN) g_dinv[side * NN + i] = rsqrtf((float)v + 1.f);
    int x = v;
    #pragma unroll
    for (int o = 1; o < 32; o <<= 1) {
        int y = __shfl_up_sync(0xffffffffu, x, o);
        if ((tid & 31) >= o) x += y;
    }
    if ((tid & 31) == 31) wsum[tid >> 5] = x;
    __syncthreads();
    if (tid == 0) {
        int run = 0;
        #pragma unroll
        for (int w = 0; w < 8; w++) { int t = wsum[w]; wsum[w] = run; run += t; }
        g_bsum[side * 512 + blockIdx.x] = run;
    }
    __syncthreads();
    if (i < NN) g_rowptr[side * NN + i] = (x - v) + wsum[tid >> 5];
}

__global__ void __launch_bounds__(512) k_scan2() {
    __shared__ int wsum[16];
    int side = blockIdx.x;
    int tid = threadIdx.x;
    int v = (tid < NB) ? g_bsum[side * 512 + tid] : 0;
    int x = v;
    #pragma unroll
    for (int o = 1; o < 32; o <<= 1) {
        int y = __shfl_up_sync(0xffffffffu, x, o);
        if ((tid & 31) >= o) x += y;
    }
    if ((tid & 31) == 31) wsum[tid >> 5] = x;
    __syncthreads();
    if (tid == 0) {
        int run = 0;
        #pragma unroll
        for (int w = 0; w < 16; w++) { int t = wsum[w]; wsum[w] = run; run += t; }
    }
    __syncthreads();
    if (tid < NB) g_bsum[side * 512 + tid] = (x - v) + wsum[tid >> 5];
}

__global__ void k_scan3() {
    int side = blockIdx.y;
    int i = blockIdx.x * 256 + threadIdx.x;
    if (i < NN) {
        int r = g_rowptr[side * NN + i] + g_bsum[side * 512 + (i >> 8)];
        g_rowptr[side * NN + i] = r;
        g_cursor[side * NN + i] = r;
    }
}

__global__ void k_fill(const int* __restrict__ e1, const int* __restrict__ e2) {
    int side = blockIdx.y;
    const int* ei = side ? e2 : e1;
    int e = blockIdx.x * 256 + threadIdx.x;
    if (e >= EE) return;
    int src = ei[e];
    int dst = ei[EE + e];
    int pos = atomicAdd(&g_cursor[side * NN + dst], 1);
    float w = g_dinv[side * NN + src] * g_dinv[side * NN + dst];
    g_cw[side * EE + pos] = make_int2(src, __float_as_int(w));
}

// ---------------- pre-layer: f = gsn(features @ preW + b); a[:,0:64] ---------
__global__ void __launch_bounds__(256) k_pre(const float* __restrict__ ft1,
                                             const float* __restrict__ ft2,
                                             const float* __restrict__ W,
                                             const float* __restrict__ b,
                                             const int* __restrict__ bt1,
                                             const int* __restrict__ bt2,
                                             const float* __restrict__ delta) {
    __shared__ float Ws[LL * HH];
    __shared__ float xs[16 * LL];
    int side = blockIdx.y;
    const float* feats = side ? ft2 : ft1;
    const int* batch = side ? bt2 : bt1;
    int tid = threadIdx.x;
    int r0 = blockIdx.x * 16;
    float4* Ws4 = (float4*)Ws;
    const float4* Wg = (const float4*)W;
    for (int i = tid; i < LL * HH / 4; i += 256) Ws4[i] = Wg[i];
    float4* xs4 = (float4*)xs;
    const float4* fg = (const float4*)(feats + (size_t)r0 * LL);
    for (int i = tid; i < 16 * (LL / 4); i += 256) xs4[i] = fg[i];
    __syncthreads();
    int row = tid >> 4, cq = tid & 15;
    float4 acc = make_float4(0.f, 0.f, 0.f, 0.f);
    #pragma unroll
    for (int k = 0; k < LL; k++) {
        float xv = xs[row * LL + k];
        float4 w = Ws4[k * 16 + cq];
        acc.x += xv * w.x; acc.y += xv * w.y; acc.z += xv * w.z; acc.w += xv * w.w;
    }
    int n = r0 + row;
    int bg = batch[n];
    float cnt = (float)(g_gstart[side * (GG + 1) + bg + 1] - g_gstart[side * (GG + 1) + bg]);
    float sc = rsqrtf(fmaxf(cnt, 1.f));
    float4 bb = ((const float4*)b)[cq];
    float4 v;
    v.x = (acc.x + bb.x) * sc; v.y = (acc.y + bb.y) * sc;
    v.z = (acc.z + bb.z) * sc; v.w = (acc.w + bb.w) * sc;
    ((float4*)g_f)[(side * NN + n) * 16 + cq] = v;
    float dd = 1.f + delta[0];
    float4 a0;
    a0.x = v.x * dd; a0.y = v.y * dd; a0.z = v.z * dd; a0.w = v.w * dd;
    ((float4*)g_a)[((size_t)side * NN + n) * 64 + cq] = a0;
}

// ---------------- mm: xw = f @ W  (fp32 math, bf16 store) --------------------
__global__ void __launch_bounds__(256) k_mm(const float* __restrict__ W) {
    __shared__ float xs[64 * 64];
    __shared__ float ws[64 * 64];
    int side = blockIdx.y;
    int t = threadIdx.x;
    int r0 = blockIdx.x * 64;
    int nrows = min(64, NN - r0);
    const float4* Wg = (const float4*)W;
    float4* ws4 = (float4*)ws;
    for (int i = t; i < 1024; i += 256) ws4[i] = Wg[i];
    const float4* fg = (const float4*)g_f;
    float4* xs4 = (float4*)xs;
    for (int p = 0; p < 4; p++) {
        int idx = p * 256 + t;
        int r = idx >> 4, kq = idx & 15;
        float4 v = (r < nrows) ? fg[(side * NN + r0 + r) * 16 + kq]
                               : make_float4(0.f, 0.f, 0.f, 0.f);
        xs4[idx] = v;
    }
    __syncthreads();
    int tr = t >> 4, tc = t & 15;
    unsigned long long acc[4][2];
    #pragma unroll
    for (int i = 0; i < 4; i++) { acc[i][0] = 0ull; acc[i][1] = 0ull; }
    #pragma unroll 4
    for (int k = 0; k < 64; k++) {
        float4 wv = ((float4*)ws)[k * 16 + tc];
        unsigned long long w01 = pack2(wv.x, wv.y);
        unsigned long long w23 = pack2(wv.z, wv.w);
        #pragma unroll
        for (int i = 0; i < 4; i++) {
            float xv = xs[(tr * 4 + i) * 64 + k];
            unsigned long long xp = pack2(xv, xv);
            fma2(acc[i][0], xp, w01);
            fma2(acc[i][1], xp, w23);
        }
    }
    uint2* xb = (uint2*)g_xwb;
    #pragma unroll
    for (int i = 0; i < 4; i++) {
        int r = r0 + tr * 4 + i;
        if (r >= NN) continue;
        float2 a0 = unpack2(acc[i][0]);
        float2 a1 = unpack2(acc[i][1]);
        __nv_bfloat162 h0 = __float22bfloat162_rn(a0);
        __nv_bfloat162 h1 = __float22bfloat162_rn(a1);
        uint2 u;
        u.x = *reinterpret_cast<unsigned*>(&h0);
        u.y = *reinterpret_cast<unsigned*>(&h1);
        xb[(side * NN + r) * 16 + tc] = u;
    }
}

// ------- gather + epilogue: a_part = relu(agg+b)+f (or raw for last) ---------
__global__ void __launch_bounds__(256) k_gather(const float* __restrict__ b,
                                                int layer) {
    int side = blockIdx.y;
    int tid = threadIdx.x;
    int grp = tid >> 4;
    int lane16 = tid & 15;
    int n = blockIdx.x * 16 + grp;
    int s = g_rowptr[side * NN + n];
    int cnt = g_deg[side * NN + n];
    const uint2* xb = (const uint2*)g_xwb;
    float di = g_dinv[side * NN + n];
    float d2 = di * di;
    float4 acc;
    {
        uint2 u = xb[(side * NN + n) * 16 + lane16];
        float2 f0 = __bfloat1622float2(*reinterpret_cast<__nv_bfloat162*>(&u.x));
        float2 f1 = __bfloat1622float2(*reinterpret_cast<__nv_bfloat162*>(&u.y));
        acc = make_float4(f0.x * d2, f0.y * d2, f1.x * d2, f1.y * d2);
    }
    unsigned mask = 0xFFFFu << (tid & 16);
    const int2* cwp = g_cw + side * EE;
    for (int c = 0; c < cnt; c += 16) {
        int idx = c + lane16;
        int2 cw = (idx < cnt) ? cwp[s + idx] : make_int2(0, 0);
        int lim = min(16, cnt - c);
        for (int j = 0; j < lim; j++) {
            int col = __shfl_sync(mask, cw.x, j, 16);
            float w = __int_as_float(__shfl_sync(mask, cw.y, j, 16));
            uint2 u = xb[(side * NN + col) * 16 + lane16];
            float2 f0 = __bfloat1622float2(*reinterpret_cast<__nv_bfloat162*>(&u.x));
            float2 f1 = __bfloat1622float2(*reinterpret_cast<__nv_bfloat162*>(&u.y));
            acc.x += w * f0.x; acc.y += w * f0.y;
            acc.z += w * f1.x; acc.w += w * f1.y;
        }
    }
    float4 bb = ((const float4*)b)[lane16];
    float4 o;
    o.x = acc.x + bb.x; o.y = acc.y + bb.y;
    o.z = acc.z + bb.z; o.w = acc.w + bb.w;
    if (layer < 2) {
        float4 f = ((float4*)g_f)[(side * NN + n) * 16 + lane16];
        float4 nf;
        nf.x = fmaxf(o.x, 0.f) + f.x; nf.y = fmaxf(o.y, 0.f) + f.y;
        nf.z = fmaxf(o.z, 0.f) + f.z; nf.w = fmaxf(o.w, 0.f) + f.w;
        ((float4*)g_f)[(side * NN + n) * 16 + lane16] = nf;
        ((float4*)g_a)[((size_t)side * NN + n) * 64 + (layer + 1) * 16 + lane16] = nf;
    } else {
        ((float4*)g_a)[((size_t)side * NN + n) * 64 + 48 + lane16] = o;
    }
}

// ---------------- sum pool ----------------------------------------------------
__global__ void __launch_bounds__(256) k_sumpool() {
    __shared__ float sm[8 * 256];
    int side = blockIdx.z;
    int g = blockIdx.x;
    int s = g_gstart[side * (GG + 1) + g], e = g_gstart[side * (GG + 1) + g + 1];
    int wid = threadIdx.x >> 5, lane = threadIdx.x & 31;
    int wg = blockIdx.y * 8 + wid;
    float acc[8];
    #pragma unroll
    for (int j = 0; j < 8; j++) acc[j] = 0.f;
    const float* ab = g_a + (size_t)side * NN * DD;
    for (int r = s + wg; r < e; r += SB * 8) {
        const float4* row = (const float4*)(ab + (size_t)r * DD);
        float4 v0 = row[lane * 2], v1 = row[lane * 2 + 1];
        acc[0] += v0.x; acc[1] += v0.y; acc[2] += v0.z; acc[3] += v0.w;
        acc[4] += v1.x; acc[5] += v1.y; acc[6] += v1.z; acc[7] += v1.w;
    }
    #pragma unroll
    for (int j = 0; j < 8; j++) sm[wid * 256 + lane * 8 + j] = acc[j];
    __syncthreads();
    int t = threadIdx.x;
    float ssum = 0.f;
    #pragma unroll
    for (int w = 0; w < 8; w++) ssum += sm[w * 256 + t];
    atomicAdd(&g_sum[side * GG * DD + g * DD + t], ssum);
}

// ---------------- ctx = tanh((sum/cnt) @ attW) -------------------------------
__global__ void __launch_bounds__(256) k_ctx(const float* __restrict__ attW) {
    __shared__ float srow[DD];
    int side = blockIdx.y;
    int g = blockIdx.x, tid = threadIdx.x;
    float c = fmaxf((float)(g_gstart[side * (GG + 1) + g + 1] - g_gstart[side * (GG + 1) + g]), 1.f);
    srow[tid] = g_sum[side * GG * DD + g * DD + tid] / c;
    __syncthreads();
    float acc = 0.f;
    for (int k = 0; k < DD; k++) acc += srow[k] * attW[k * DD + tid];
    g_t[side * GG * DD + g * DD + tid] = tanhf(acc);
}

// ---------------- attention pool ---------------------------------------------
__global__ void __launch_bounds__(256) k_attpool() {
    __shared__ float sm[8 * 256];
    int side = blockIdx.z;
    int g = blockIdx.x;
    int s = g_gstart[side * (GG + 1) + g], e = g_gstart[side * (GG + 1) + g + 1];
    int wid = threadIdx.x >> 5, lane = threadIdx.x & 31;
    int wg = blockIdx.y * 8 + wid;
    float tval[8];
    #pragma unroll
    for (int j = 0; j < 8; j++) tval[j] = g_t[side * GG * DD + g * DD + lane * 8 + j];
    float acc[8];
    #pragma unroll
    for (int j = 0; j < 8; j++) acc[j] = 0.f;
    const float* ab = g_a + (size_t)side * NN * DD;
    for (int r = s + wg; r < e; r += SB * 8) {
        const float4* row = (const float4*)(ab + (size_t)r * DD);
        float4 v0 = row[lane * 2], v1 = row[lane * 2 + 1];
        float dot = v0.x * tval[0] + v0.y * tval[1] + v0.z * tval[2] + v0.w * tval[3]
                  + v1.x * tval[4] + v1.y * tval[5] + v1.z * tval[6] + v1.w * tval[7];
        #pragma unroll
        for (int o = 16; o; o >>= 1) dot += __shfl_xor_sync(0xffffffffu, dot, o);
        float coef = 1.f / (1.f + expf(-dot));
        acc[0] += v0.x * coef; acc[1] += v0.y * coef;
        acc[2] += v0.z * coef; acc[3] += v0.w * coef;
        acc[4] += v1.x * coef; acc[5] += v1.y * coef;
        acc[6] += v1.z * coef; acc[7] += v1.w * coef;
    }
    #pragma unroll
    for (int j = 0; j < 8; j++) sm[wid * 256 + lane * 8 + j] = acc[j];
    __syncthreads();
    int t = threadIdx.x;
    float ssum = 0.f;
    #pragma unroll
    for (int w = 0; w < 8; w++) ssum += sm[w * 256 + t];
    atomicAdd(&g_att[side * GG * DD + g * DD + t], ssum);
}

// ---------------- mix + post-MLP ---------------------------------------------
__global__ void __launch_bounds__(128) k_mlp(const float* __restrict__ mu,
                                             const float* __restrict__ W1, const float* __restrict__ b1,
                                             const float* __restrict__ W2, const float* __restrict__ b2) {
    __shared__ float prow[DD];
    __shared__ float hid[128];
    int side = blockIdx.y;
    int g = blockIdx.x, tid = threadIdx.x;
    {
        int base = side * GG * DD + g * DD;
        float m0 = mu[tid], m1 = mu[tid + 128];
        prow[tid] = m0 * g_att[base + tid] + (1.f - m0) * g_sum[base + tid];
        prow[tid + 128] = m1 * g_att[base + tid + 128] + (1.f - m1) * g_sum[base + tid + 128];
    }
    __syncthreads();
    float h = b1[tid];
    for (int k = 0; k < DD; k++) h += prow[k] * W1[k * 128 + tid];
    hid[tid] = fmaxf(h, 0.f);
    __syncthreads();
    if (tid < HH) {
        float o = b2[tid];
        for (int k = 0; k < 128; k++) o += hid[k] * W2[k * HH + tid];
        g_gh[side * GG * HH + g * HH + tid] = o;
    }
}

// ---------------- final NTN + scoring ----------------------------------------
__global__ void __launch_bounds__(64) k_score(const float* __restrict__ tnW,
                                              const float* __restrict__ tnV,
                                              const float* __restrict__ tnb,
                                              const float* __restrict__ scW1,
                                              const float* __restrict__ scb1,
                                              const float* __restrict__ scW2,
                                              const float* __restrict__ scb2,
                                              const float* __restrict__ alpha,
                                              float* __restrict__ out) {
    __shared__ float gxs[HH], hxs[HH], t1s[TNW], scs[TNW], hid[TNW];
    __shared__ float l2s;
    int g = blockIdx.x, e = threadIdx.x;
    gxs[e] = g_gh[g * HH + e];
    hxs[e] = g_gh[GG * HH + g * HH + e];
    if (e < TNW) t1s[e] = 0.f;
    if (e == 0) l2s = 0.f;
    __syncthreads();
    float acc[TNW];
    #pragma unroll
    for (int k = 0; k < TNW; k++) acc[k] = 0.f;
    for (int d = 0; d < HH; d++) {
        float gd = gxs[d];
        const float4* wp = (const float4*)(tnW + (d * HH + e) * TNW);
        float4 w0 = wp[0], w1 = wp[1], w2 = wp[2], w3 = wp[3];
        acc[0]  += gd * w0.x; acc[1]  += gd * w0.y; acc[2]  += gd * w0.z; acc[3]  += gd * w0.w;
        acc[4]  += gd * w1.x; acc[5]  += gd * w1.y; acc[6]  += gd * w1.z; acc[7]  += gd * w1.w;
        acc[8]  += gd * w2.x; acc[9]  += gd * w2.y; acc[10] += gd * w2.z; acc[11] += gd * w2.w;
        acc[12] += gd * w3.x; acc[13] += gd * w3.y; acc[14] += gd * w3.z; acc[15] += gd * w3.w;
    }
    float hx = hxs[e];
    #pragma unroll
    for (int k = 0; k < TNW; k++) {
        float s = acc[k] * hx;
        #pragma unroll
        for (int o = 16; o; o >>= 1) s += __shfl_xor_sync(0xffffffffu, s, o);
        if ((e & 31) == 0) atomicAdd(&t1s[k], s);
    }
    float df = gxs[e] - hxs[e];
    float s2 = df * df;
    #pragma unroll
    for (int o = 16; o; o >>= 1) s2 += __shfl_xor_sync(0xffffffffu, s2, o);
    if ((e & 31) == 0) atomicAdd(&l2s, s2);
    __syncthreads();
    if (e < TNW) {
        float t2 = tnb[e];
        for (int j = 0; j < HH; j++) t2 += gxs[j] * tnV[e * 2 * HH + j];
        for (int j = 0; j < HH; j++) t2 += hxs[j] * tnV[e * 2 * HH + HH + j];
        scs[e] = fmaxf(t1s[e] + t2, 0.f);
    }
    __syncthreads();
    if (e < TNW) {
        float h = scb1[e];
        for (int j = 0; j < TNW; j++) h += scs[j] * scW1[j * TNW + e];
        hid[e] = fmaxf(h, 0.f);
    }
    __syncthreads();
    if (e == 0) {
        float sc = scb2[0];
        for (int j = 0; j < TNW; j++) sc += hid[j] * scW2[j];
        float l2 = sqrtf(l2s);
        float al = alpha[0];
        out[g] = al * (1.f / (1.f + expf(-sc))) + (1.f - al) * (1.f / (1.f + expf(l2)));
    }
}

// ---------------- launch ------------------------------------------------------
extern "C" void kernel_launch(void* const* d_in, const int* in_sizes, int n_in,
                              void* d_out, int out_size) {
    const int* ei1    = (const int*)d_in[0];
    const int* ei2    = (const int*)d_in[1];
    const int* bt1    = (const int*)d_in[2];
    const int* bt2    = (const int*)d_in[3];
    const float* ft1  = (const float*)d_in[4];
    const float* ft2  = (const float*)d_in[5];
    const float* preW  = (const float*)d_in[6];
    const float* preb  = (const float*)d_in[7];
    const float* convW = (const float*)d_in[8];
    const float* convb = (const float*)d_in[9];
    const float* delta = (const float*)d_in[10];
    const float* alpha = (const float*)d_in[11];
    const float* mu    = (const float*)d_in[12];
    const float* attW  = (const float*)d_in[13];
    const float* pW1   = (const float*)d_in[14];
    const float* pb1   = (const float*)d_in[15];
    const float* pW2   = (const float*)d_in[16];
    const float* pb2   = (const float*)d_in[17];
    const float* tnW   = (const float*)d_in[18];
    const float* tnV   = (const float*)d_in[19];
    const float* tnb   = (const float*)d_in[20];
    const float* scW1  = (const float*)d_in[21];
    const float* scb1  = (const float*)d_in[22];
    const float* scW2  = (const float*)d_in[23];
    const float* scb2  = (const float*)d_in[24];
    float* out = (float*)d_out;

    k_init<<<dim3(NB, 2), 256>>>(bt1, bt2);
    k_deg<<<dim3(EB, 2), 256>>>(ei1, ei2);
    k_scan1<<<dim3(NB, 2), 256>>>();
    k_scan2<<<2, 512>>>();
    k_scan3<<<dim3(NB, 2), 256>>>();
    k_fill<<<dim3(EB, 2), 256>>>(ei1, ei2);
    k_pre<<<dim3(GB, 2), 256>>>(ft1, ft2, preW, preb, bt1, bt2, delta);
    for (int i = 0; i < 3; i++) {
        k_mm<<<dim3(MMB, 2), 256>>>(convW + i * HH * HH);
        k_gather<<<dim3(GB, 2), 256>>>(convb + i * HH, i);
    }
    k_sumpool<<<dim3(GG, SB, 2), 256>>>();
    k_ctx<<<dim3(GG, 2), 256>>>(attW);
    k_attpool<<<dim3(GG, SB, 2), 256>>>();
    k_mlp<<<dim3(GG, 2), 128>>>(mu, pW1, pb1, pW2, pb2);
    k_score<<<GG, 64>>>(tnW, tnV, tnb, scW1, scb1, scW2, scb2, alpha, out);
}

// round 7
// speedup vs baseline: 1.9306x; 1.2076x over previous
#include <cuda_runtime.h>
#include <cuda_bf16.h>
#include <math.h>

#define NN 100000
#define EE 1600000
#define GG 128
#define LL 32
#define HH 64
#define DD 256
#define TNW 16

#define NB   ((NN + 255) / 256)     // 391
#define EB   ((EE + 255) / 256)     // 6250
#define GB   (NN / 16)              // 6250 gather blocks
#define MMB  ((NN + 63) / 64)       // 1563
#define SB   6                      // sub-blocks per graph for pooling

// ---------------- scratch (static device globals; no allocation) -------------
__device__ float         g_f[2 * NN * HH];
__device__ __nv_bfloat16 g_xwb[2 * NN * HH];
__device__ __nv_bfloat16 g_a[2 * (size_t)NN * DD];   // concat buffer in bf16
__device__ int   g_deg[2 * NN];
__device__ float g_dinv[2 * NN];
__device__ int   g_rowptr[2 * NN];
__device__ int   g_cursor[2 * NN];
__device__ int   g_bsum[2 * 512];
__device__ int2  g_cw[2 * EE];
__device__ int   g_gstart[2 * (GG + 1)];
__device__ float g_sum[2 * GG * DD];
__device__ float g_att[2 * GG * DD];
__device__ float g_t[2 * GG * DD];
__device__ float g_gh[2 * GG * HH];

// ---------------- f32x2 / bf16 helpers ---------------------------------------
__device__ __forceinline__ void fma2(unsigned long long& d, unsigned long long a,
                                     unsigned long long b) {
    asm("fma.rn.f32x2 %0, %1, %2, %0;" : "+l"(d) : "l"(a), "l"(b));
}
__device__ __forceinline__ unsigned long long pack2(float lo, float hi) {
    unsigned long long r;
    asm("mov.b64 %0, {%1, %2};" : "=l"(r) : "f"(lo), "f"(hi));
    return r;
}
__device__ __forceinline__ float2 unpack2(unsigned long long v) {
    float2 r;
    asm("mov.b64 {%0, %1}, %2;" : "=f"(r.x), "=f"(r.y) : "l"(v));
    return r;
}
__device__ __forceinline__ uint2 f4_to_bf4(float4 v) {
    __nv_bfloat162 h0 = __float22bfloat162_rn(make_float2(v.x, v.y));
    __nv_bfloat162 h1 = __float22bfloat162_rn(make_float2(v.z, v.w));
    uint2 u;
    u.x = *reinterpret_cast<unsigned*>(&h0);
    u.y = *reinterpret_cast<unsigned*>(&h1);
    return u;
}

// ---------------- init: zero deg/sum/att + graph start offsets ---------------
__global__ void k_init(const int* __restrict__ b1, const int* __restrict__ b2) {
    int side = blockIdx.y;
    const int* batch = side ? b2 : b1;
    int i = blockIdx.x * 256 + threadIdx.x;
    if (i < NN) {
        g_deg[side * NN + i] = 0;
        int b = batch[i];
        int prev = (i > 0) ? batch[i - 1] : -1;
        for (int g = prev + 1; g <= b; g++) g_gstart[side * (GG + 1) + g] = i;
        if (i == NN - 1)
            for (int g = b + 1; g <= GG; g++) g_gstart[side * (GG + 1) + g] = NN;
    }
    if (i < GG * DD) { g_sum[side * GG * DD + i] = 0.f; g_att[side * GG * DD + i] = 0.f; }
}

__global__ void k_deg(const int* __restrict__ e1, const int* __restrict__ e2) {
    int side = blockIdx.y;
    const int* ei = side ? e2 : e1;
    int e = blockIdx.x * 256 + threadIdx.x;
    if (e < EE) atomicAdd(&g_deg[side * NN + ei[EE + e]], 1);
}

// ---------------- CSR build: scans + atomic fill -----------------------------
__global__ void k_scan1() {
    __shared__ int wsum[8];
    int side = blockIdx.y;
    int tid = threadIdx.x;
    int i = blockIdx.x * 256 + tid;
    int v = (i < NN) ? g_deg[side * NN + i] : 0;
    if (i < NN) g_dinv[side * NN + i] = rsqrtf((float)v + 1.f);
    int x = v;
    #pragma unroll
    for (int o = 1; o < 32; o <<= 1) {
        int y = __shfl_up_sync(0xffffffffu, x, o);
        if ((tid & 31) >= o) x += y;
    }
    if ((tid & 31) == 31) wsum[tid >> 5] = x;
    __syncthreads();
    if (tid == 0) {
        int run = 0;
        #pragma unroll
        for (int w = 0; w < 8; w++) { int t = wsum[w]; wsum[w] = run; run += t; }
        g_bsum[side * 512 + blockIdx.x] = run;
    }
    __syncthreads();
    if (i < NN) g_rowptr[side * NN + i] = (x - v) + wsum[tid >> 5];
}

__global__ void __launch_bounds__(512) k_scan2() {
    __shared__ int wsum[16];
    int side = blockIdx.x;
    int tid = threadIdx.x;
    int v = (tid < NB) ? g_bsum[side * 512 + tid] : 0;
    int x = v;
    #pragma unroll
    for (int o = 1; o < 32; o <<= 1) {
        int y = __shfl_up_sync(0xffffffffu, x, o);
        if ((tid & 31) >= o) x += y;
    }
    if ((tid & 31) == 31) wsum[tid >> 5] = x;
    __syncthreads();
    if (tid == 0) {
        int run = 0;
        #pragma unroll
        for (int w = 0; w < 16; w++) { int t = wsum[w]; wsum[w] = run; run += t; }
    }
    __syncthreads();
    if (tid < NB) g_bsum[side * 512 + tid] = (x - v) + wsum[tid >> 5];
}

__global__ void k_scan3() {
    int side = blockIdx.y;
    int i = blockIdx.x * 256 + threadIdx.x;
    if (i < NN) {
        int r = g_rowptr[side * NN + i] + g_bsum[side * 512 + (i >> 8)];
        g_rowptr[side * NN + i] = r;
        g_cursor[side * NN + i] = r;
    }
}

__global__ void k_fill(const int* __restrict__ e1, const int* __restrict__ e2) {
    int side = blockIdx.y;
    const int* ei = side ? e2 : e1;
    int e = blockIdx.x * 256 + threadIdx.x;
    if (e >= EE) return;
    int src = ei[e];
    int dst = ei[EE + e];
    int pos = atomicAdd(&g_cursor[side * NN + dst], 1);
    float w = g_dinv[side * NN + src] * g_dinv[side * NN + dst];
    g_cw[side * EE + pos] = make_int2(src, __float_as_int(w));
}

// ---------------- pre-layer: f = gsn(features @ preW + b); a[:,0:64] ---------
__global__ void __launch_bounds__(256) k_pre(const float* __restrict__ ft1,
                                             const float* __restrict__ ft2,
                                             const float* __restrict__ W,
                                             const float* __restrict__ b,
                                             const int* __restrict__ bt1,
                                             const int* __restrict__ bt2,
                                             const float* __restrict__ delta) {
    __shared__ float Ws[LL * HH];
    __shared__ float xs[16 * LL];
    int side = blockIdx.y;
    const float* feats = side ? ft2 : ft1;
    const int* batch = side ? bt2 : bt1;
    int tid = threadIdx.x;
    int r0 = blockIdx.x * 16;
    float4* Ws4 = (float4*)Ws;
    const float4* Wg = (const float4*)W;
    for (int i = tid; i < LL * HH / 4; i += 256) Ws4[i] = Wg[i];
    float4* xs4 = (float4*)xs;
    const float4* fg = (const float4*)(feats + (size_t)r0 * LL);
    for (int i = tid; i < 16 * (LL / 4); i += 256) xs4[i] = fg[i];
    __syncthreads();
    int row = tid >> 4, cq = tid & 15;
    float4 acc = make_float4(0.f, 0.f, 0.f, 0.f);
    #pragma unroll
    for (int k = 0; k < LL; k++) {
        float xv = xs[row * LL + k];
        float4 w = Ws4[k * 16 + cq];
        acc.x += xv * w.x; acc.y += xv * w.y; acc.z += xv * w.z; acc.w += xv * w.w;
    }
    int n = r0 + row;
    int bg = batch[n];
    float cnt = (float)(g_gstart[side * (GG + 1) + bg + 1] - g_gstart[side * (GG + 1) + bg]);
    float sc = rsqrtf(fmaxf(cnt, 1.f));
    float4 bb = ((const float4*)b)[cq];
    float4 v;
    v.x = (acc.x + bb.x) * sc; v.y = (acc.y + bb.y) * sc;
    v.z = (acc.z + bb.z) * sc; v.w = (acc.w + bb.w) * sc;
    ((float4*)g_f)[(side * NN + n) * 16 + cq] = v;
    float dd = 1.f + delta[0];
    float4 a0;
    a0.x = v.x * dd; a0.y = v.y * dd; a0.z = v.z * dd; a0.w = v.w * dd;
    ((uint2*)g_a)[((size_t)side * NN + n) * 64 + cq] = f4_to_bf4(a0);
}

// ---------------- mm: xw = f @ W  (fp32 math, bf16 store) --------------------
__global__ void __launch_bounds__(256) k_mm(const float* __restrict__ W) {
    __shared__ float xs[64 * 64];
    __shared__ float ws[64 * 64];
    int side = blockIdx.y;
    int t = threadIdx.x;
    int r0 = blockIdx.x * 64;
    int nrows = min(64, NN - r0);
    const float4* Wg = (const float4*)W;
    float4* ws4 = (float4*)ws;
    for (int i = t; i < 1024; i += 256) ws4[i] = Wg[i];
    const float4* fg = (const float4*)g_f;
    float4* xs4 = (float4*)xs;
    for (int p = 0; p < 4; p++) {
        int idx = p * 256 + t;
        int r = idx >> 4, kq = idx & 15;
        float4 v = (r < nrows) ? fg[(side * NN + r0 + r) * 16 + kq]
                               : make_float4(0.f, 0.f, 0.f, 0.f);
        xs4[idx] = v;
    }
    __syncthreads();
    int tr = t >> 4, tc = t & 15;
    unsigned long long acc[4][2];
    #pragma unroll
    for (int i = 0; i < 4; i++) { acc[i][0] = 0ull; acc[i][1] = 0ull; }
    const float4* xs4c = (const float4*)xs;
    const float4* ws4c = (const float4*)ws;
    #pragma unroll 4
    for (int k4 = 0; k4 < 16; k4++) {
        float xr[4][4];
        #pragma unroll
        for (int i = 0; i < 4; i++) {
            float4 v = xs4c[(tr * 4 + i) * 16 + k4];
            xr[i][0] = v.x; xr[i][1] = v.y; xr[i][2] = v.z; xr[i][3] = v.w;
        }
        #pragma unroll
        for (int kk = 0; kk < 4; kk++) {
            float4 wv = ws4c[(k4 * 4 + kk) * 16 + tc];
            unsigned long long w01 = pack2(wv.x, wv.y);
            unsigned long long w23 = pack2(wv.z, wv.w);
            #pragma unroll
            for (int i = 0; i < 4; i++) {
                unsigned long long xp = pack2(xr[i][kk], xr[i][kk]);
                fma2(acc[i][0], xp, w01);
                fma2(acc[i][1], xp, w23);
            }
        }
    }
    uint2* xb = (uint2*)g_xwb;
    #pragma unroll
    for (int i = 0; i < 4; i++) {
        int r = r0 + tr * 4 + i;
        if (r >= NN) continue;
        float2 a0 = unpack2(acc[i][0]);
        float2 a1 = unpack2(acc[i][1]);
        xb[(side * NN + r) * 16 + tc] = f4_to_bf4(make_float4(a0.x, a0.y, a1.x, a1.y));
    }
}

// ------- gather + epilogue: a_part = relu(agg+b)+f (or raw for last) ---------
__global__ void __launch_bounds__(256) k_gather(const float* __restrict__ b,
                                                int layer) {
    int side = blockIdx.y;
    int tid = threadIdx.x;
    int grp = tid >> 4;
    int lane16 = tid & 15;
    int n = blockIdx.x * 16 + grp;
    int s = g_rowptr[side * NN + n];
    int cnt = g_deg[side * NN + n];
    const uint2* xb = (const uint2*)g_xwb;
    float di = g_dinv[side * NN + n];
    float d2 = di * di;
    float4 acc;
    {
        uint2 u = xb[(side * NN + n) * 16 + lane16];
        float2 f0 = __bfloat1622float2(*reinterpret_cast<__nv_bfloat162*>(&u.x));
        float2 f1 = __bfloat1622float2(*reinterpret_cast<__nv_bfloat162*>(&u.y));
        acc = make_float4(f0.x * d2, f0.y * d2, f1.x * d2, f1.y * d2);
    }
    unsigned mask = 0xFFFFu << (tid & 16);
    const int2* cwp = g_cw + side * EE;
    for (int c = 0; c < cnt; c += 16) {
        int idx = c + lane16;
        int2 cw = (idx < cnt) ? cwp[s + idx] : make_int2(0, 0);
        int lim = min(16, cnt - c);
        for (int j = 0; j < lim; j++) {
            int col = __shfl_sync(mask, cw.x, j, 16);
            float w = __int_as_float(__shfl_sync(mask, cw.y, j, 16));
            uint2 u = xb[(side * NN + col) * 16 + lane16];
            float2 f0 = __bfloat1622float2(*reinterpret_cast<__nv_bfloat162*>(&u.x));
            float2 f1 = __bfloat1622float2(*reinterpret_cast<__nv_bfloat162*>(&u.y));
            acc.x += w * f0.x; acc.y += w * f0.y;
            acc.z += w * f1.x; acc.w += w * f1.y;
        }
    }
    float4 bb = ((const float4*)b)[lane16];
    float4 o;
    o.x = acc.x + bb.x; o.y = acc.y + bb.y;
    o.z = acc.z + bb.z; o.w = acc.w + bb.w;
    uint2* ab2 = (uint2*)g_a;
    if (layer < 2) {
        float4 f = ((float4*)g_f)[(side * NN + n) * 16 + lane16];
        float4 nf;
        nf.x = fmaxf(o.x, 0.f) + f.x; nf.y = fmaxf(o.y, 0.f) + f.y;
        nf.z = fmaxf(o.z, 0.f) + f.z; nf.w = fmaxf(o.w, 0.f) + f.w;
        ((float4*)g_f)[(side * NN + n) * 16 + lane16] = nf;
        ab2[((size_t)side * NN + n) * 64 + (layer + 1) * 16 + lane16] = f4_to_bf4(nf);
    } else {
        ab2[((size_t)side * NN + n) * 64 + 48 + lane16] = f4_to_bf4(o);
    }
}

// ---------------- sum pool (bf16 reads) --------------------------------------
__global__ void __launch_bounds__(256) k_sumpool() {
    __shared__ float sm[8 * 256];
    int side = blockIdx.z;
    int g = blockIdx.x;
    int s = g_gstart[side * (GG + 1) + g], e = g_gstart[side * (GG + 1) + g + 1];
    int wid = threadIdx.x >> 5, lane = threadIdx.x & 31;
    int wg = blockIdx.y * 8 + wid;
    float acc[8];
    #pragma unroll
    for (int j = 0; j < 8; j++) acc[j] = 0.f;
    const __nv_bfloat16* ab = g_a + (size_t)side * NN * DD;
    for (int r = s + wg; r < e; r += SB * 8) {
        uint4 u = ((const uint4*)(ab + (size_t)r * DD))[lane];
        float2 p0 = __bfloat1622float2(*reinterpret_cast<__nv_bfloat162*>(&u.x));
        float2 p1 = __bfloat1622float2(*reinterpret_cast<__nv_bfloat162*>(&u.y));
        float2 p2 = __bfloat1622float2(*reinterpret_cast<__nv_bfloat162*>(&u.z));
        float2 p3 = __bfloat1622float2(*reinterpret_cast<__nv_bfloat162*>(&u.w));
        acc[0] += p0.x; acc[1] += p0.y; acc[2] += p1.x; acc[3] += p1.y;
        acc[4] += p2.x; acc[5] += p2.y; acc[6] += p3.x; acc[7] += p3.y;
    }
    #pragma unroll
    for (int j = 0; j < 8; j++) sm[wid * 256 + lane * 8 + j] = acc[j];
    __syncthreads();
    int t = threadIdx.x;
    float ssum = 0.f;
    #pragma unroll
    for (int w = 0; w < 8; w++) ssum += sm[w * 256 + t];
    atomicAdd(&g_sum[side * GG * DD + g * DD + t], ssum);
}

// ---------------- ctx = tanh((sum/cnt) @ attW) -------------------------------
__global__ void __launch_bounds__(256) k_ctx(const float* __restrict__ attW) {
    __shared__ float srow[DD];
    int side = blockIdx.y;
    int g = blockIdx.x, tid = threadIdx.x;
    float c = fmaxf((float)(g_gstart[side * (GG + 1) + g + 1] - g_gstart[side * (GG + 1) + g]), 1.f);
    srow[tid] = g_sum[side * GG * DD + g * DD + tid] / c;
    __syncthreads();
    float acc = 0.f;
    for (int k = 0; k < DD; k++) acc += srow[k] * attW[k * DD + tid];
    g_t[side * GG * DD + g * DD + tid] = tanhf(acc);
}

// ---------------- attention pool (bf16 reads) --------------------------------
__global__ void __launch_bounds__(256) k_attpool() {
    __shared__ float sm[8 * 256];
    int side = blockIdx.z;
    int g = blockIdx.x;
    int s = g_gstart[side * (GG + 1) + g], e = g_gstart[side * (GG + 1) + g + 1];
    int wid = threadIdx.x >> 5, lane = threadIdx.x & 31;
    int wg = blockIdx.y * 8 + wid;
    float tval[8];
    #pragma unroll
    for (int j = 0; j < 8; j++) tval[j] = g_t[side * GG * DD + g * DD + lane * 8 + j];
    float acc[8];
    #pragma unroll
    for (int j = 0; j < 8; j++) acc[j] = 0.f;
    const __nv_bfloat16* ab = g_a + (size_t)side * NN * DD;
    for (int r = s + wg; r < e; r += SB * 8) {
        uint4 u = ((const uint4*)(ab + (size_t)r * DD))[lane];
        float2 p0 = __bfloat1622float2(*reinterpret_cast<__nv_bfloat162*>(&u.x));
        float2 p1 = __bfloat1622float2(*reinterpret_cast<__nv_bfloat162*>(&u.y));
        float2 p2 = __bfloat1622float2(*reinterpret_cast<__nv_bfloat162*>(&u.z));
        float2 p3 = __bfloat1622float2(*reinterpret_cast<__nv_bfloat162*>(&u.w));
        float v[8] = { p0.x, p0.y, p1.x, p1.y, p2.x, p2.y, p3.x, p3.y };
        float dot = 0.f;
        #pragma unroll
        for (int j = 0; j < 8; j++) dot += v[j] * tval[j];
        #pragma unroll
        for (int o = 16; o; o >>= 1) dot += __shfl_xor_sync(0xffffffffu, dot, o);
        float coef = 1.f / (1.f + expf(-dot));
        #pragma unroll
        for (int j = 0; j < 8; j++) acc[j] += v[j] * coef;
    }
    #pragma unroll
    for (int j = 0; j < 8; j++) sm[wid * 256 + lane * 8 + j] = acc[j];
    __syncthreads();
    int t = threadIdx.x;
    float ssum = 0.f;
    #pragma unroll
    for (int w = 0; w < 8; w++) ssum += sm[w * 256 + t];
    atomicAdd(&g_att[side * GG * DD + g * DD + t], ssum);
}

// ---------------- mix + post-MLP ---------------------------------------------
__global__ void __launch_bounds__(128) k_mlp(const float* __restrict__ mu,
                                             const float* __restrict__ W1, const float* __restrict__ b1,
                                             const float* __restrict__ W2, const float* __restrict__ b2) {
    __shared__ float prow[DD];
    __shared__ float hid[128];
    int side = blockIdx.y;
    int g = blockIdx.x, tid = threadIdx.x;
    {
        int base = side * GG * DD + g * DD;
        float m0 = mu[tid], m1 = mu[tid + 128];
        prow[tid] = m0 * g_att[base + tid] + (1.f - m0) * g_sum[base + tid];
        prow[tid + 128] = m1 * g_att[base + tid + 128] + (1.f - m1) * g_sum[base + tid + 128];
    }
    __syncthreads();
    float h = b1[tid];
    for (int k = 0; k < DD; k++) h += prow[k] * W1[k * 128 + tid];
    hid[tid] = fmaxf(h, 0.f);
    __syncthreads();
    if (tid < HH) {
        float o = b2[tid];
        for (int k = 0; k < 128; k++) o += hid[k] * W2[k * HH + tid];
        g_gh[side * GG * HH + g * HH + tid] = o;
    }
}

// ---------------- final NTN + scoring ----------------------------------------
__global__ void __launch_bounds__(64) k_score(const float* __restrict__ tnW,
                                              const float* __restrict__ tnV,
                                              const float* __restrict__ tnb,
                                              const float* __restrict__ scW1,
                                              const float* __restrict__ scb1,
                                              const float* __restrict__ scW2,
                                              const float* __restrict__ scb2,
                                              const float* __restrict__ alpha,
                                              float* __restrict__ out) {
    __shared__ float gxs[HH], hxs[HH], t1s[TNW], scs[TNW], hid[TNW];
    __shared__ float l2s;
    int g = blockIdx.x, e = threadIdx.x;
    gxs[e] = g_gh[g * HH + e];
    hxs[e] = g_gh[GG * HH + g * HH + e];
    if (e < TNW) t1s[e] = 0.f;
    if (e == 0) l2s = 0.f;
    __syncthreads();
    float acc[TNW];
    #pragma unroll
    for (int k = 0; k < TNW; k++) acc[k] = 0.f;
    for (int d = 0; d < HH; d++) {
        float gd = gxs[d];
        const float4* wp = (const float4*)(tnW + (d * HH + e) * TNW);
        float4 w0 = wp[0], w1 = wp[1], w2 = wp[2], w3 = wp[3];
        acc[0]  += gd * w0.x; acc[1]  += gd * w0.y; acc[2]  += gd * w0.z; acc[3]  += gd * w0.w;
        acc[4]  += gd * w1.x; acc[5]  += gd * w1.y; acc[6]  += gd * w1.z; acc[7]  += gd * w1.w;
        acc[8]  += gd * w2.x; acc[9]  += gd * w2.y; acc[10] += gd * w2.z; acc[11] += gd * w2.w;
        acc[12] += gd * w3.x; acc[13] += gd * w3.y; acc[14] += gd * w3.z; acc[15] += gd * w3.w;
    }
    float hx = hxs[e];
    #pragma unroll
    for (int k = 0; k < TNW; k++) {
        float s = acc[k] * hx;
        #pragma unroll
        for (int o = 16; o; o >>= 1) s += __shfl_xor_sync(0xffffffffu, s, o);
        if ((e & 31) == 0) atomicAdd(&t1s[k], s);
    }
    float df = gxs[e] - hxs[e];
    float s2 = df * df;
    #pragma unroll
    for (int o = 16; o; o >>= 1) s2 += __shfl_xor_sync(0xffffffffu, s2, o);
    if ((e & 31) == 0) atomicAdd(&l2s, s2);
    __syncthreads();
    if (e < TNW) {
        float t2 = tnb[e];
        for (int j = 0; j < HH; j++) t2 += gxs[j] * tnV[e * 2 * HH + j];
        for (int j = 0; j < HH; j++) t2 += hxs[j] * tnV[e * 2 * HH + HH + j];
        scs[e] = fmaxf(t1s[e] + t2, 0.f);
    }
    __syncthreads();
    if (e < TNW) {
        float h = scb1[e];
        for (int j = 0; j < TNW; j++) h += scs[j] * scW1[j * TNW + e];
        hid[e] = fmaxf(h, 0.f);
    }
    __syncthreads();
    if (e == 0) {
        float sc = scb2[0];
        for (int j = 0; j < TNW; j++) sc += hid[j] * scW2[j];
        float l2 = sqrtf(l2s);
        float al = alpha[0];
        out[g] = al * (1.f / (1.f + expf(-sc))) + (1.f - al) * (1.f / (1.f + expf(l2)));
    }
}

// ---------------- launch ------------------------------------------------------
extern "C" void kernel_launch(void* const* d_in, const int* in_sizes, int n_in,
                              void* d_out, int out_size) {
    const int* ei1    = (const int*)d_in[0];
    const int* ei2    = (const int*)d_in[1];
    const int* bt1    = (const int*)d_in[2];
    const int* bt2    = (const int*)d_in[3];
    const float* ft1  = (const float*)d_in[4];
    const float* ft2  = (const float*)d_in[5];
    const float* preW  = (const float*)d_in[6];
    const float* preb  = (const float*)d_in[7];
    const float* convW = (const float*)d_in[8];
    const float* convb = (const float*)d_in[9];
    const float* delta = (const float*)d_in[10];
    const float* alpha = (const float*)d_in[11];
    const float* mu    = (const float*)d_in[12];
    const float* attW  = (const float*)d_in[13];
    const float* pW1   = (const float*)d_in[14];
    const float* pb1   = (const float*)d_in[15];
    const float* pW2   = (const float*)d_in[16];
    const float* pb2   = (const float*)d_in[17];
    const float* tnW   = (const float*)d_in[18];
    const float* tnV   = (const float*)d_in[19];
    const float* tnb   = (const float*)d_in[20];
    const float* scW1  = (const float*)d_in[21];
    const float* scb1  = (const float*)d_in[22];
    const float* scW2  = (const float*)d_in[23];
    const float* scb2  = (const float*)d_in[24];
    float* out = (float*)d_out;

    k_init<<<dim3(NB, 2), 256>>>(bt1, bt2);
    k_deg<<<dim3(EB, 2), 256>>>(ei1, ei2);
    k_scan1<<<dim3(NB, 2), 256>>>();
    k_scan2<<<2, 512>>>();
    k_scan3<<<dim3(NB, 2), 256>>>();
    k_fill<<<dim3(EB, 2), 256>>>(ei1, ei2);
    k_pre<<<dim3(GB, 2), 256>>>(ft1, ft2, preW, preb, bt1, bt2, delta);
    for (int i = 0; i < 3; i++) {
        k_mm<<<dim3(MMB, 2), 256>>>(convW + i * HH * HH);
        k_gather<<<dim3(GB, 2), 256>>>(convb + i * HH, i);
    }
    k_sumpool<<<dim3(GG, SB, 2), 256>>>();
    k_ctx<<<dim3(GG, 2), 256>>>(attW);
    k_attpool<<<dim3(GG, SB, 2), 256>>>();
    k_mlp<<<dim3(GG, 2), 128>>>(mu, pW1, pb1, pW2, pb2);
    k_score<<<GG, 64>>>(tnW, tnV, tnb, scW1, scb1, scW2, scb2, alpha, out);
}